// round 8
// baseline (speedup 1.0000x reference)
#include <cuda_runtime.h>
#include <math.h>

// ---------------- problem constants ----------------
#define BATCH 4
#define NPTS  2048
#define NNODE 8192                // BATCH*NPTS
#define ERAND 131072              // NNODE*16
#define ETOT  (ERAND + NNODE)     // + self loops
#define OUTC  1792                // 256+512+1024

// ---------------- scratch (static device memory; referenced directly) -----
__device__ float bufFused[NNODE * 128];
__device__ float bufF1[NNODE * 256];
__device__ float bufF2[NNODE * 512];
__device__ float bufF3[NNODE * 1024];
__device__ float bufXL[NNODE * 1024];
__device__ float bufXR[NNODE * 1024];
__device__ int   bufDeg[NNODE];
__device__ int   bufRowPtr[NNODE + 1];
__device__ int   bufCursor[NNODE];
__device__ int   bufCsrSrc[ETOT];
__device__ int   bufCsrDst[ETOT];
__device__ float bufE[ETOT];
__device__ float bufAlpha[ETOT];

// buffer selectors (device-side only)
__device__ __forceinline__ const float* featBuf(int s) {
    switch (s) {
        case 0:  return bufFused;
        case 1:  return bufF1;
        case 2:  return bufF2;
        default: return bufF3;
    }
}
__device__ __forceinline__ float* featBufW(int s) {
    switch (s) {
        case 1:  return bufF1;
        case 2:  return bufF2;
        default: return bufF3;
    }
}
__device__ __forceinline__ float* xBuf(int s) { return s ? bufXR : bufXL; }

// ---------------- fuse: conv1d(3->64) || conv1d(32->64), relu -------------
__global__ void fuse_kernel(const float* __restrict__ x,
                            const float* __restrict__ emb,
                            const float* __restrict__ gw, const float* __restrict__ gb,
                            const float* __restrict__ cw, const float* __restrict__ cb) {
    int node = blockIdx.x;              // 0..8191
    int b = node / NPTS, n = node % NPTS;
    __shared__ float sx[3];
    __shared__ float se[32];
    int tid = threadIdx.x;              // 128 threads
    if (tid < 3)            sx[tid]    = x[(size_t)b * 3 * NPTS + tid * NPTS + n];
    else if (tid < 35)      se[tid-3]  = emb[(size_t)b * 32 * NPTS + (tid - 3) * NPTS + n];
    __syncthreads();
    float v;
    if (tid < 64) {
        v = gb[tid];
        #pragma unroll
        for (int k = 0; k < 3; k++) v += sx[k] * gw[k * 64 + tid];
    } else {
        int c = tid - 64;
        v = cb[c];
        #pragma unroll
        for (int k = 0; k < 32; k++) v += se[k] * cw[k * 64 + c];
    }
    bufFused[(size_t)node * 128 + tid] = fmaxf(v, 0.0f);
}

// ---------------- CSR build (edge_index is int32: JAX x64 disabled) -------
__global__ void zero_deg_kernel() {
    int i = blockIdx.x * blockDim.x + threadIdx.x;
    if (i < NNODE) bufDeg[i] = 0;
}

__global__ void count_kernel(const int* __restrict__ ei) {
    int e = blockIdx.x * blockDim.x + threadIdx.x;
    if (e >= ETOT) return;
    int dst = (e < ERAND) ? ei[ERAND + e] : (e - ERAND);
    atomicAdd(&bufDeg[dst], 1);
}

// single block, 1024 threads, 8 nodes each
__global__ void scan_kernel() {
    __shared__ int sh[1024];
    int tid = threadIdx.x;
    int base = tid * 8;
    int local[8];
    int s = 0;
    #pragma unroll
    for (int i = 0; i < 8; i++) { local[i] = s; s += bufDeg[base + i]; }
    sh[tid] = s;
    __syncthreads();
    for (int off = 1; off < 1024; off <<= 1) {
        int v = (tid >= off) ? sh[tid - off] : 0;
        __syncthreads();
        sh[tid] += v;
        __syncthreads();
    }
    int prev = tid ? sh[tid - 1] : 0;
    #pragma unroll
    for (int i = 0; i < 8; i++) {
        bufRowPtr[base + i] = prev + local[i];
        bufCursor[base + i] = prev + local[i];
    }
    if (tid == 1023) bufRowPtr[NNODE] = sh[1023];
}

__global__ void fill_kernel(const int* __restrict__ ei) {
    int e = blockIdx.x * blockDim.x + threadIdx.x;
    if (e >= ETOT) return;
    int src, dst;
    if (e < ERAND) { src = ei[e]; dst = ei[ERAND + e]; }
    else           { src = e - ERAND;  dst = src; }
    int pos = atomicAdd(&bufCursor[dst], 1);
    bufCsrSrc[pos] = src;
    bufCsrDst[pos] = dst;
}

// ---------------- SGEMM: C[M,N] = A[M,K] @ B[K,N] + bias ------------------
// 128x128 tile, BK=8, 256 threads, 8x8 microtile.
__global__ __launch_bounds__(256, 2)
void sgemm_kernel(int aSel, const float* __restrict__ B,
                  const float* __restrict__ bias, int cSel,
                  int N, int K) {
    const float* A = featBuf(aSel);
    float* C = xBuf(cSel);
    __shared__ float As[8][128];
    __shared__ float Bs[8][128];
    const int tid = threadIdx.x;
    const int brow = blockIdx.y, bcol = blockIdx.x;
    const int tr = tid >> 4, tc = tid & 15;

    float acc[8][8];
    #pragma unroll
    for (int i = 0; i < 8; i++)
        #pragma unroll
        for (int j = 0; j < 8; j++) acc[i][j] = 0.0f;

    const int aRow = tid >> 1;            // 0..127
    const int aCol = (tid & 1) * 4;       // 0 or 4
    const int bRow = tid >> 5;            // 0..7
    const int bCol = (tid & 31) * 4;      // 0..124

    const float* Ap = A + (size_t)(brow * 128 + aRow) * K + aCol;
    const float* Bp = B + (size_t)bRow * N + bcol * 128 + bCol;

    for (int k0 = 0; k0 < K; k0 += 8) {
        float4 av = *(const float4*)(Ap + k0);
        As[aCol + 0][aRow] = av.x;
        As[aCol + 1][aRow] = av.y;
        As[aCol + 2][aRow] = av.z;
        As[aCol + 3][aRow] = av.w;
        float4 bv = *(const float4*)(Bp + (size_t)k0 * N);
        *(float4*)&Bs[bRow][bCol] = bv;
        __syncthreads();
        #pragma unroll
        for (int kk = 0; kk < 8; kk++) {
            float ar[8], br[8];
            *(float4*)&ar[0] = *(const float4*)&As[kk][tr * 8];
            *(float4*)&ar[4] = *(const float4*)&As[kk][tr * 8 + 4];
            *(float4*)&br[0] = *(const float4*)&Bs[kk][tc * 8];
            *(float4*)&br[4] = *(const float4*)&Bs[kk][tc * 8 + 4];
            #pragma unroll
            for (int i = 0; i < 8; i++)
                #pragma unroll
                for (int j = 0; j < 8; j++)
                    acc[i][j] = fmaf(ar[i], br[j], acc[i][j]);
        }
        __syncthreads();
    }

    const int rbase = brow * 128 + tr * 8;
    const int cbase = bcol * 128 + tc * 8;
    #pragma unroll
    for (int i = 0; i < 8; i++) {
        float* Cr = C + (size_t)(rbase + i) * N + cbase;
        #pragma unroll
        for (int j = 0; j < 8; j++)
            Cr[j] = acc[i][j] + bias[cbase + j];
    }
}

// ---------------- edge logits: e = att . leakyrelu(xl[src] + xr[dst]) -----
__global__ void logit_kernel(const float* __restrict__ att, int F) {
    int gid = blockIdx.x * blockDim.x + threadIdx.x;
    int slot = gid >> 5;
    int lane = gid & 31;
    if (slot >= ETOT) return;
    int src = bufCsrSrc[slot];
    int dst = bufCsrDst[slot];
    const float* pl = bufXL + (size_t)src * F;
    const float* pr = bufXR + (size_t)dst * F;
    float sum = 0.0f;
    for (int f = lane; f < F; f += 32) {
        float v = pl[f] + pr[f];
        v = (v > 0.0f) ? v : 0.2f * v;
        sum = fmaf(v, att[f], sum);
    }
    #pragma unroll
    for (int o = 16; o; o >>= 1) sum += __shfl_xor_sync(0xffffffffu, sum, o);
    if (lane == 0) bufE[slot] = sum;
}

// ---------------- per-node segment softmax ----------------
__global__ void softmax_kernel() {
    int gid = blockIdx.x * blockDim.x + threadIdx.x;
    int node = gid >> 5;
    int lane = gid & 31;
    if (node >= NNODE) return;
    int beg = bufRowPtr[node], end = bufRowPtr[node + 1];
    float m = -1e30f;
    for (int s = beg + lane; s < end; s += 32) m = fmaxf(m, bufE[s]);
    #pragma unroll
    for (int o = 16; o; o >>= 1) m = fmaxf(m, __shfl_xor_sync(0xffffffffu, m, o));
    float sum = 0.0f;
    for (int s = beg + lane; s < end; s += 32) sum += __expf(bufE[s] - m);
    #pragma unroll
    for (int o = 16; o; o >>= 1) sum += __shfl_xor_sync(0xffffffffu, sum, o);
    float inv = 1.0f / sum;
    for (int s = beg + lane; s < end; s += 32) bufAlpha[s] = __expf(bufE[s] - m) * inv;
}

// ---------------- aggregation: out[v] = sum alpha*xl[src] + bias, opt relu -
__global__ void aggregate_kernel(const float* __restrict__ bias,
                                 int outSel,                       // -1 = none, 1..3
                                 float* __restrict__ out2,         // may be null (slice of d_out)
                                 int out2_stride, int F, int doRelu) {
    __shared__ float s_a[128];
    __shared__ int   s_src[128];
    float* out = (outSel >= 0) ? featBufW(outSel) : nullptr;
    int node = blockIdx.x;
    int tid = threadIdx.x;                 // 128 threads
    int nf = F >> 7;                       // F/128 <= 8
    float acc[8];
    #pragma unroll
    for (int i = 0; i < 8; i++) acc[i] = 0.0f;

    int beg = bufRowPtr[node], end = bufRowPtr[node + 1];
    for (int c0 = beg; c0 < end; c0 += 128) {
        int cnt = min(128, end - c0);
        if (tid < cnt) { s_a[tid] = bufAlpha[c0 + tid]; s_src[tid] = bufCsrSrc[c0 + tid]; }
        __syncthreads();
        for (int s = 0; s < cnt; s++) {
            float a = s_a[s];
            const float* row = bufXL + (size_t)s_src[s] * F;
            #pragma unroll
            for (int i = 0; i < 8; i++)
                if (i < nf) acc[i] = fmaf(a, row[tid + i * 128], acc[i]);
        }
        __syncthreads();
    }
    #pragma unroll
    for (int i = 0; i < 8; i++) {
        if (i >= nf) break;
        int c = tid + i * 128;
        float v = acc[i] + bias[c];
        if (doRelu) v = fmaxf(v, 0.0f);
        if (out)  out[(size_t)node * F + c] = v;
        if (out2) out2[(size_t)node * out2_stride + c] = v;
    }
}

// ---------------- host orchestration ----------------
static void run_gat_layer(int featSel, int K, int F,
                          const float* Wl, const float* bl,
                          const float* Wr, const float* br,
                          const float* att, const float* bias,
                          int outSel, float* out2, int doRelu) {
    dim3 ggrid(F / 128, NNODE / 128);
    sgemm_kernel<<<ggrid, 256>>>(featSel, Wl, bl, 0 /*XL*/, F, K);
    sgemm_kernel<<<ggrid, 256>>>(featSel, Wr, br, 1 /*XR*/, F, K);
    logit_kernel<<<(ETOT * 32 + 255) / 256, 256>>>(att, F);
    softmax_kernel<<<(NNODE * 32) / 256, 256>>>();
    aggregate_kernel<<<NNODE, 128>>>(bias, outSel, out2, OUTC, F, doRelu);
}

extern "C" void kernel_launch(void* const* d_in, const int* in_sizes, int n_in,
                              void* d_out, int out_size) {
    const float* x    = (const float*)d_in[0];
    const float* emb  = (const float*)d_in[1];
    const int*   ei   = (const int*)d_in[2];   // int32! (JAX x64 disabled)
    const float* gw = (const float*)d_in[3];
    const float* gb = (const float*)d_in[4];
    const float* cw = (const float*)d_in[5];
    const float* cb = (const float*)d_in[6];

    const float *Wl[4], *bl[4], *Wr[4], *br[4], *att[4], *bias[4];
    for (int i = 0; i < 4; i++) {
        Wl[i]   = (const float*)d_in[7 + 6 * i + 0];
        bl[i]   = (const float*)d_in[7 + 6 * i + 1];
        Wr[i]   = (const float*)d_in[7 + 6 * i + 2];
        br[i]   = (const float*)d_in[7 + 6 * i + 3];
        att[i]  = (const float*)d_in[7 + 6 * i + 4];
        bias[i] = (const float*)d_in[7 + 6 * i + 5];
    }
    float* out = (float*)d_out;

    // stage 0: fused features + CSR build
    fuse_kernel<<<NNODE, 128>>>(x, emb, gw, gb, cw, cb);
    zero_deg_kernel<<<NNODE / 256, 256>>>();
    count_kernel<<<(ETOT + 255) / 256, 256>>>(ei);
    scan_kernel<<<1, 1024>>>();
    fill_kernel<<<(ETOT + 255) / 256, 256>>>(ei);

    // 4 GATv2 layers
    run_gat_layer(0, 128,  256, Wl[0], bl[0], Wr[0], br[0], att[0], bias[0],
                  1, out + 0, 1);
    run_gat_layer(1, 256,  512, Wl[1], bl[1], Wr[1], br[1], att[1], bias[1],
                  2, out + 256, 1);
    run_gat_layer(2, 512, 1024, Wl[2], bl[2], Wr[2], br[2], att[2], bias[2],
                  3, nullptr, 1);
    run_gat_layer(3, 1024, 1024, Wl[3], bl[3], Wr[3], br[3], att[3], bias[3],
                  -1, out + 768, 0);
}

// round 11
// speedup vs baseline: 1.9695x; 1.9695x over previous
#include <cuda_runtime.h>
#include <cuda_bf16.h>
#include <math.h>
#include <stdint.h>

// ---------------- problem constants ----------------
#define NPTS  2048
#define NNODE 8192                // 4*2048
#define ERAND 131072              // NNODE*16
#define ETOT  (ERAND + NNODE)     // + self loops
#define OUTC  1792                // 256+512+1024
#define KMAX  1024

// ---------------- scratch (static device memory) ----------------
__device__ float bufFused[NNODE * 128];
__device__ float bufF1[NNODE * 256];
__device__ float bufF2[NNODE * 512];
__device__ float bufF3[NNODE * 1024];
__device__ float bufXL[NNODE * 1024];
__device__ float bufXR[NNODE * 1024];
__device__ __nv_bfloat16 bufAhi[NNODE * KMAX];
__device__ __nv_bfloat16 bufAlo[NNODE * KMAX];
__device__ __nv_bfloat16 bufWthi[2048 * KMAX];   // [2F, K] K-major, Wl^T || Wr^T
__device__ __nv_bfloat16 bufWtlo[2048 * KMAX];
__device__ int   bufDeg[NNODE];
__device__ int   bufRowPtr[NNODE + 1];
__device__ int   bufCursor[NNODE];
__device__ int   bufCsrSrc[ETOT];
__device__ int   bufCsrDst[ETOT];
__device__ float bufE[ETOT];
__device__ float bufAlpha[ETOT];

__device__ __forceinline__ const float* featBuf(int s) {
    switch (s) {
        case 0:  return bufFused;
        case 1:  return bufF1;
        case 2:  return bufF2;
        default: return bufF3;
    }
}
__device__ __forceinline__ float* featBufW(int s) {
    switch (s) {
        case 1:  return bufF1;
        case 2:  return bufF2;
        default: return bufF3;
    }
}

// ---------------- fuse: conv1d(3->64) || conv1d(32->64), relu -------------
__global__ void fuse_kernel(const float* __restrict__ x,
                            const float* __restrict__ emb,
                            const float* __restrict__ gw, const float* __restrict__ gb,
                            const float* __restrict__ cw, const float* __restrict__ cb) {
    int node = blockIdx.x;
    int b = node / NPTS, n = node % NPTS;
    __shared__ float sx[3];
    __shared__ float se[32];
    int tid = threadIdx.x;              // 128
    if (tid < 3)            sx[tid]    = x[(size_t)b * 3 * NPTS + tid * NPTS + n];
    else if (tid < 35)      se[tid-3]  = emb[(size_t)b * 32 * NPTS + (tid - 3) * NPTS + n];
    __syncthreads();
    float v;
    if (tid < 64) {
        v = gb[tid];
        #pragma unroll
        for (int k = 0; k < 3; k++) v += sx[k] * gw[k * 64 + tid];
    } else {
        int c = tid - 64;
        v = cb[c];
        #pragma unroll
        for (int k = 0; k < 32; k++) v += se[k] * cw[k * 64 + c];
    }
    bufFused[(size_t)node * 128 + tid] = fmaxf(v, 0.0f);
}

// ---------------- CSR build (edge_index is int32) ----------------
__global__ void zero_deg_kernel() {
    int i = blockIdx.x * blockDim.x + threadIdx.x;
    if (i < NNODE) bufDeg[i] = 0;
}
__global__ void count_kernel(const int* __restrict__ ei) {
    int e = blockIdx.x * blockDim.x + threadIdx.x;
    if (e >= ETOT) return;
    int dst = (e < ERAND) ? ei[ERAND + e] : (e - ERAND);
    atomicAdd(&bufDeg[dst], 1);
}
__global__ void scan_kernel() {
    __shared__ int sh[1024];
    int tid = threadIdx.x;
    int base = tid * 8;
    int local[8];
    int s = 0;
    #pragma unroll
    for (int i = 0; i < 8; i++) { local[i] = s; s += bufDeg[base + i]; }
    sh[tid] = s;
    __syncthreads();
    for (int off = 1; off < 1024; off <<= 1) {
        int v = (tid >= off) ? sh[tid - off] : 0;
        __syncthreads();
        sh[tid] += v;
        __syncthreads();
    }
    int prev = tid ? sh[tid - 1] : 0;
    #pragma unroll
    for (int i = 0; i < 8; i++) {
        bufRowPtr[base + i] = prev + local[i];
        bufCursor[base + i] = prev + local[i];
    }
    if (tid == 1023) bufRowPtr[NNODE] = sh[1023];
}
__global__ void fill_kernel(const int* __restrict__ ei) {
    int e = blockIdx.x * blockDim.x + threadIdx.x;
    if (e >= ETOT) return;
    int src, dst;
    if (e < ERAND) { src = ei[e]; dst = ei[ERAND + e]; }
    else           { src = e - ERAND;  dst = src; }
    int pos = atomicAdd(&bufCursor[dst], 1);
    bufCsrSrc[pos] = src;
    bufCsrDst[pos] = dst;
}

// ---------------- split-bf16 conversion ----------------
__global__ void convertA_kernel(int featSel, int total) {
    int i = blockIdx.x * blockDim.x + threadIdx.x;
    if (i >= total) return;
    float v = featBuf(featSel)[i];
    __nv_bfloat16 hi = __float2bfloat16(v);
    __nv_bfloat16 lo = __float2bfloat16(v - __bfloat162float(hi));
    bufAhi[i] = hi;
    bufAlo[i] = lo;
}

// Wt[n, k]: n < F -> Wl[k*F+n], else Wr[k*F+(n-F)]. K contiguous per row.
__global__ void convertW_kernel(const float* __restrict__ Wl, const float* __restrict__ Wr,
                                int K, int F) {
    int i = blockIdx.x * blockDim.x + threadIdx.x;
    if (i >= 2 * F * K) return;
    int n = i / K, k = i % K;
    float v = (n < F) ? Wl[(size_t)k * F + n] : Wr[(size_t)k * F + (n - F)];
    __nv_bfloat16 hi = __float2bfloat16(v);
    __nv_bfloat16 lo = __float2bfloat16(v - __bfloat162float(hi));
    bufWthi[i] = hi;
    bufWtlo[i] = lo;
}

// ---------------- mma.sync split-bf16 GEMM ----------------
// C[8192, 2F] = A[8192, K] @ Wt^T  (3 MMAs: hi*hi + lo*hi + hi*lo), fp32 acc.
// CTA: 256 threads (8 warps, 2x4), tile 128(M) x 128(N), K chunk 64.
#define TSTRIDE 72                       // bf16 per smem row (144B, conflict-free)
#define TILE_ELEMS (128 * TSTRIDE)
#define SM_TOTAL_G (4 * TILE_ELEMS * 2)  // 73728 bytes

__device__ __forceinline__ uint32_t s2u(const void* p) {
    return (uint32_t)__cvta_generic_to_shared(p);
}
__device__ __forceinline__ void ldsm4(uint32_t* r, uint32_t addr) {
    asm volatile("ldmatrix.sync.aligned.m8n8.x4.shared.b16 {%0,%1,%2,%3}, [%4];"
                 : "=r"(r[0]), "=r"(r[1]), "=r"(r[2]), "=r"(r[3]) : "r"(addr));
}
__device__ __forceinline__ void ldsm2(uint32_t* r, uint32_t addr) {
    asm volatile("ldmatrix.sync.aligned.m8n8.x2.shared.b16 {%0,%1}, [%2];"
                 : "=r"(r[0]), "=r"(r[1]) : "r"(addr));
}
__device__ __forceinline__ void mma_bf16(float* d, const uint32_t* a, const uint32_t* b) {
    asm volatile(
        "mma.sync.aligned.m16n8k16.row.col.f32.bf16.bf16.f32 "
        "{%0,%1,%2,%3}, {%4,%5,%6,%7}, {%8,%9}, {%0,%1,%2,%3};"
        : "+f"(d[0]), "+f"(d[1]), "+f"(d[2]), "+f"(d[3])
        : "r"(a[0]), "r"(a[1]), "r"(a[2]), "r"(a[3]), "r"(b[0]), "r"(b[1]));
}

__global__ __launch_bounds__(256, 1)
void gemm_dual_kernel(int K, int F,
                      const float* __restrict__ bl, const float* __restrict__ br) {
    extern __shared__ __nv_bfloat16 smem[];
    __nv_bfloat16* sAhi = smem;
    __nv_bfloat16* sAlo = smem + TILE_ELEMS;
    __nv_bfloat16* sBhi = smem + 2 * TILE_ELEMS;
    __nv_bfloat16* sBlo = smem + 3 * TILE_ELEMS;

    const int tid  = threadIdx.x;
    const int wid  = tid >> 5, lane = tid & 31;
    const int wm   = wid >> 2;            // 0..1 -> +64 rows
    const int wn   = wid & 3;             // 0..3 -> +32 cols
    const int n0   = blockIdx.x * 128;    // col in [0, 2F)
    const int m0   = blockIdx.y * 128;    // row in [0, NNODE)
    const int side = (n0 >= F) ? 1 : 0;
    float* outp = side ? bufXR : bufXL;
    const float* bp = side ? br : bl;
    const int colBase = n0 - side * F;

    float acc[4][4][4];
    #pragma unroll
    for (int mt = 0; mt < 4; mt++)
        #pragma unroll
        for (int nt = 0; nt < 4; nt++)
            #pragma unroll
            for (int q = 0; q < 4; q++) acc[mt][nt][q] = 0.0f;

    // ldmatrix addresses (per-thread constants within the k-step loop)
    const int aRow = wm * 64 + (lane & 7) + ((lane >> 3) & 1) * 8; // + mt*16
    const int aCol = (lane >> 4) * 8;                              // + ks*16
    const int bRow = wn * 32 + (lane & 7);                         // + nt*8
    const int bCol = ((lane >> 3) & 1) * 8;                        // + ks*16

    for (int c0 = 0; c0 < K; c0 += 64) {
        __syncthreads();
        // load 4 tiles: 128 rows x 64 bf16, vectorized uint4 (8 bf16)
        #pragma unroll
        for (int i = 0; i < 4; i++) {
            int v = tid + i * 256;
            int r = v >> 3, c8 = (v & 7) * 8;
            sAhi[r * TSTRIDE + c8 + 0] = sAhi[r * TSTRIDE + c8];   // dummy to keep indices (overwritten)
            *(uint4*)(sAhi + r * TSTRIDE + c8) =
                *(const uint4*)(bufAhi + (size_t)(m0 + r) * K + c0 + c8);
            *(uint4*)(sAlo + r * TSTRIDE + c8) =
                *(const uint4*)(bufAlo + (size_t)(m0 + r) * K + c0 + c8);
            *(uint4*)(sBhi + r * TSTRIDE + c8) =
                *(const uint4*)(bufWthi + (size_t)(n0 + r) * K + c0 + c8);
            *(uint4*)(sBlo + r * TSTRIDE + c8) =
                *(const uint4*)(bufWtlo + (size_t)(n0 + r) * K + c0 + c8);
        }
        __syncthreads();

        #pragma unroll
        for (int ks = 0; ks < 4; ks++) {
            uint32_t ah[4][4], al[4][4];
            #pragma unroll
            for (int mt = 0; mt < 4; mt++) {
                int off = (aRow + mt * 16) * TSTRIDE + aCol + ks * 16;
                ldsm4(ah[mt], s2u(sAhi + off));
                ldsm4(al[mt], s2u(sAlo + off));
            }
            uint32_t bh[4][2], bo[4][2];
            #pragma unroll
            for (int nt = 0; nt < 4; nt++) {
                int off = (bRow + nt * 8) * TSTRIDE + bCol + ks * 16;
                ldsm2(bh[nt], s2u(sBhi + off));
                ldsm2(bo[nt], s2u(sBlo + off));
            }
            #pragma unroll
            for (int mt = 0; mt < 4; mt++)
                #pragma unroll
                for (int nt = 0; nt < 4; nt++) {
                    mma_bf16(acc[mt][nt], ah[mt], bh[nt]);
                    mma_bf16(acc[mt][nt], al[mt], bh[nt]);
                    mma_bf16(acc[mt][nt], ah[mt], bo[nt]);
                }
        }
    }

    // epilogue: add bias, write XL or XR
    #pragma unroll
    for (int mt = 0; mt < 4; mt++) {
        int r = m0 + wm * 64 + mt * 16 + (lane >> 2);
        #pragma unroll
        for (int nt = 0; nt < 4; nt++) {
            int c = colBase + wn * 32 + nt * 8 + (lane & 3) * 2;
            float b0 = bp[c], b1 = bp[c + 1];
            float* o0 = outp + (size_t)r * F + c;
            o0[0] = acc[mt][nt][0] + b0;
            o0[1] = acc[mt][nt][1] + b1;
            float* o1 = o0 + (size_t)8 * F;
            o1[0] = acc[mt][nt][2] + b0;
            o1[1] = acc[mt][nt][3] + b1;
        }
    }
}

// ---------------- edge logits ----------------
__global__ void logit_kernel(const float* __restrict__ att, int F) {
    int gid = blockIdx.x * blockDim.x + threadIdx.x;
    int slot = gid >> 5;
    int lane = gid & 31;
    if (slot >= ETOT) return;
    int src = bufCsrSrc[slot];
    int dst = bufCsrDst[slot];
    const float* pl = bufXL + (size_t)src * F;
    const float* pr = bufXR + (size_t)dst * F;
    float sum = 0.0f;
    for (int f = lane; f < F; f += 32) {
        float v = pl[f] + pr[f];
        v = (v > 0.0f) ? v : 0.2f * v;
        sum = fmaf(v, att[f], sum);
    }
    #pragma unroll
    for (int o = 16; o; o >>= 1) sum += __shfl_xor_sync(0xffffffffu, sum, o);
    if (lane == 0) bufE[slot] = sum;
}

// ---------------- per-node segment softmax ----------------
__global__ void softmax_kernel() {
    int gid = blockIdx.x * blockDim.x + threadIdx.x;
    int node = gid >> 5;
    int lane = gid & 31;
    if (node >= NNODE) return;
    int beg = bufRowPtr[node], end = bufRowPtr[node + 1];
    float m = -1e30f;
    for (int s = beg + lane; s < end; s += 32) m = fmaxf(m, bufE[s]);
    #pragma unroll
    for (int o = 16; o; o >>= 1) m = fmaxf(m, __shfl_xor_sync(0xffffffffu, m, o));
    float sum = 0.0f;
    for (int s = beg + lane; s < end; s += 32) sum += __expf(bufE[s] - m);
    #pragma unroll
    for (int o = 16; o; o >>= 1) sum += __shfl_xor_sync(0xffffffffu, sum, o);
    float inv = 1.0f / sum;
    for (int s = beg + lane; s < end; s += 32) bufAlpha[s] = __expf(bufE[s] - m) * inv;
}

// ---------------- aggregation ----------------
__global__ void aggregate_kernel(const float* __restrict__ bias,
                                 int outSel, float* __restrict__ out2,
                                 int out2_stride, int F, int doRelu) {
    __shared__ float s_a[128];
    __shared__ int   s_src[128];
    float* out = (outSel >= 0) ? featBufW(outSel) : nullptr;
    int node = blockIdx.x;
    int tid = threadIdx.x;                 // 128
    int nf = F >> 7;
    float acc[8];
    #pragma unroll
    for (int i = 0; i < 8; i++) acc[i] = 0.0f;

    int beg = bufRowPtr[node], end = bufRowPtr[node + 1];
    for (int c0 = beg; c0 < end; c0 += 128) {
        int cnt = min(128, end - c0);
        if (tid < cnt) { s_a[tid] = bufAlpha[c0 + tid]; s_src[tid] = bufCsrSrc[c0 + tid]; }
        __syncthreads();
        for (int s = 0; s < cnt; s++) {
            float a = s_a[s];
            const float* row = bufXL + (size_t)s_src[s] * F;
            #pragma unroll
            for (int i = 0; i < 8; i++)
                if (i < nf) acc[i] = fmaf(a, row[tid + i * 128], acc[i]);
        }
        __syncthreads();
    }
    #pragma unroll
    for (int i = 0; i < 8; i++) {
        if (i >= nf) break;
        int c = tid + i * 128;
        float v = acc[i] + bias[c];
        if (doRelu) v = fmaxf(v, 0.0f);
        if (out)  out[(size_t)node * F + c] = v;
        if (out2) out2[(size_t)node * out2_stride + c] = v;
    }
}

// ---------------- host orchestration ----------------
static void run_gat_layer(int featSel, int K, int F,
                          const float* Wl, const float* bl,
                          const float* Wr, const float* br,
                          const float* att, const float* bias,
                          int outSel, float* out2, int doRelu) {
    convertA_kernel<<<(NNODE * K) / 256, 256>>>(featSel, NNODE * K);
    convertW_kernel<<<(2 * F * K) / 256, 256>>>(Wl, Wr, K, F);
    dim3 ggrid((2 * F) / 128, NNODE / 128);
    gemm_dual_kernel<<<ggrid, 256, SM_TOTAL_G>>>(K, F, bl, br);
    logit_kernel<<<(ETOT * 32 + 255) / 256, 256>>>(att, F);
    softmax_kernel<<<(NNODE * 32) / 256, 256>>>();
    aggregate_kernel<<<NNODE, 128>>>(bias, outSel, out2, OUTC, F, doRelu);
}

extern "C" void kernel_launch(void* const* d_in, const int* in_sizes, int n_in,
                              void* d_out, int out_size) {
    const float* x    = (const float*)d_in[0];
    const float* emb  = (const float*)d_in[1];
    const int*   ei   = (const int*)d_in[2];   // int32 (JAX x64 disabled)
    const float* gw = (const float*)d_in[3];
    const float* gb = (const float*)d_in[4];
    const float* cw = (const float*)d_in[5];
    const float* cb = (const float*)d_in[6];

    const float *Wl[4], *bl[4], *Wr[4], *br[4], *att[4], *bias[4];
    for (int i = 0; i < 4; i++) {
        Wl[i]   = (const float*)d_in[7 + 6 * i + 0];
        bl[i]   = (const float*)d_in[7 + 6 * i + 1];
        Wr[i]   = (const float*)d_in[7 + 6 * i + 2];
        br[i]   = (const float*)d_in[7 + 6 * i + 3];
        att[i]  = (const float*)d_in[7 + 6 * i + 4];
        bias[i] = (const float*)d_in[7 + 6 * i + 5];
    }
    float* out = (float*)d_out;

    cudaFuncSetAttribute(gemm_dual_kernel,
                         cudaFuncAttributeMaxDynamicSharedMemorySize, SM_TOTAL_G);

    // stage 0: fused features + CSR build
    fuse_kernel<<<NNODE, 128>>>(x, emb, gw, gb, cw, cb);
    zero_deg_kernel<<<NNODE / 256, 256>>>();
    count_kernel<<<(ETOT + 255) / 256, 256>>>(ei);
    scan_kernel<<<1, 1024>>>();
    fill_kernel<<<(ETOT + 255) / 256, 256>>>(ei);

    // 4 GATv2 layers
    run_gat_layer(0, 128,  256, Wl[0], bl[0], Wr[0], br[0], att[0], bias[0],
                  1, out + 0, 1);
    run_gat_layer(1, 256,  512, Wl[1], bl[1], Wr[1], br[1], att[1], bias[1],
                  2, out + 256, 1);
    run_gat_layer(2, 512, 1024, Wl[2], bl[2], Wr[2], br[2], att[2], bias[2],
                  3, nullptr, 1);
    run_gat_layer(3, 1024, 1024, Wl[3], bl[3], Wr[3], br[3], att[3], bias[3],
                  -1, out + 768, 0);
}

// round 14
// speedup vs baseline: 2.1974x; 1.1157x over previous
#include <cuda_runtime.h>
#include <cuda_bf16.h>
#include <math.h>
#include <stdint.h>

// ---------------- problem constants ----------------
#define NPTS  2048
#define NNODE 8192                // 4*2048
#define ERAND 131072              // NNODE*16
#define ETOT  (ERAND + NNODE)     // + self loops
#define OUTC  1792                // 256+512+1024
#define KMAX  1024

// ---------------- scratch (static device memory) ----------------
__device__ float bufXL[NNODE * 1024];
__device__ float bufXR[NNODE * 1024];
__device__ __nv_bfloat16 bufAhi[NNODE * KMAX];
__device__ __nv_bfloat16 bufAlo[NNODE * KMAX];
__device__ __nv_bfloat16 bufWthi[2048 * KMAX];   // [2F, K] K-major, Wl^T || Wr^T
__device__ __nv_bfloat16 bufWtlo[2048 * KMAX];
__device__ int   bufDeg[NNODE];
__device__ int   bufRowPtr[NNODE + 1];
__device__ int   bufCursor[NNODE];
__device__ int   bufCsrSrc[ETOT];
__device__ int   bufCsrDst[ETOT];
__device__ float bufE[ETOT];
__device__ float bufAlpha[ETOT];

// ---------------- fuse: conv1d(3->64) || conv1d(32->64), relu, split-bf16 --
__global__ void fuse_kernel(const float* __restrict__ x,
                            const float* __restrict__ emb,
                            const float* __restrict__ gw, const float* __restrict__ gb,
                            const float* __restrict__ cw, const float* __restrict__ cb) {
    int node = blockIdx.x;
    int b = node / NPTS, n = node % NPTS;
    __shared__ float sx[3];
    __shared__ float se[32];
    int tid = threadIdx.x;              // 128
    if (tid < 3)            sx[tid]    = x[(size_t)b * 3 * NPTS + tid * NPTS + n];
    else if (tid < 35)      se[tid-3]  = emb[(size_t)b * 32 * NPTS + (tid - 3) * NPTS + n];
    __syncthreads();
    float v;
    if (tid < 64) {
        v = gb[tid];
        #pragma unroll
        for (int k = 0; k < 3; k++) v += sx[k] * gw[k * 64 + tid];
    } else {
        int c = tid - 64;
        v = cb[c];
        #pragma unroll
        for (int k = 0; k < 32; k++) v += se[k] * cw[k * 64 + c];
    }
    v = fmaxf(v, 0.0f);
    __nv_bfloat16 hi = __float2bfloat16(v);
    __nv_bfloat16 lo = __float2bfloat16(v - __bfloat162float(hi));
    bufAhi[(size_t)node * 128 + tid] = hi;
    bufAlo[(size_t)node * 128 + tid] = lo;
}

// ---------------- CSR build (edge_index is int32) ----------------
__global__ void zero_deg_kernel() {
    int i = blockIdx.x * blockDim.x + threadIdx.x;
    if (i < NNODE) bufDeg[i] = 0;
}
__global__ void count_kernel(const int* __restrict__ ei) {
    int e = blockIdx.x * blockDim.x + threadIdx.x;
    if (e >= ETOT) return;
    int dst = (e < ERAND) ? ei[ERAND + e] : (e - ERAND);
    atomicAdd(&bufDeg[dst], 1);
}
__global__ void scan_kernel() {
    __shared__ int sh[1024];
    int tid = threadIdx.x;
    int base = tid * 8;
    int local[8];
    int s = 0;
    #pragma unroll
    for (int i = 0; i < 8; i++) { local[i] = s; s += bufDeg[base + i]; }
    sh[tid] = s;
    __syncthreads();
    for (int off = 1; off < 1024; off <<= 1) {
        int v = (tid >= off) ? sh[tid - off] : 0;
        __syncthreads();
        sh[tid] += v;
        __syncthreads();
    }
    int prev = tid ? sh[tid - 1] : 0;
    #pragma unroll
    for (int i = 0; i < 8; i++) {
        bufRowPtr[base + i] = prev + local[i];
        bufCursor[base + i] = prev + local[i];
    }
    if (tid == 1023) bufRowPtr[NNODE] = sh[1023];
}
__global__ void fill_kernel(const int* __restrict__ ei) {
    int e = blockIdx.x * blockDim.x + threadIdx.x;
    if (e >= ETOT) return;
    int src, dst;
    if (e < ERAND) { src = ei[e]; dst = ei[ERAND + e]; }
    else           { src = e - ERAND;  dst = src; }
    int pos = atomicAdd(&bufCursor[dst], 1);
    bufCsrSrc[pos] = src;
    bufCsrDst[pos] = dst;
}

// ---------------- weight split conversion ----------------
// Wt[n, k]: n < F -> Wl[k*F+n], else Wr[k*F+(n-F)]. K contiguous per row.
__global__ void convertW_kernel(const float* __restrict__ Wl, const float* __restrict__ Wr,
                                int K, int F) {
    int i = blockIdx.x * blockDim.x + threadIdx.x;
    if (i >= 2 * F * K) return;
    int n = i / K, k = i % K;
    float v = (n < F) ? Wl[(size_t)k * F + n] : Wr[(size_t)k * F + (n - F)];
    __nv_bfloat16 hi = __float2bfloat16(v);
    __nv_bfloat16 lo = __float2bfloat16(v - __bfloat162float(hi));
    bufWthi[i] = hi;
    bufWtlo[i] = lo;
}

// ---------------- mma.sync split-bf16 GEMM, cp.async 2-stage pipeline -----
// C[8192, 2F] = A[8192, K] @ Wt^T  (3 MMAs: hi*hi + lo*hi + hi*lo), fp32 acc.
// CTA: 256 threads (8 warps, 2x4), tile 128(M) x 128(N), K chunk 64.
#define TSTRIDE 72                        // bf16 per smem row (144B, conflict-free)
#define TILE_ELEMS (128 * TSTRIDE)
#define STAGE_ELEMS (4 * TILE_ELEMS)
#define SM_TOTAL_G (2 * STAGE_ELEMS * 2)  // 147456 bytes

__device__ __forceinline__ uint32_t s2u(const void* p) {
    return (uint32_t)__cvta_generic_to_shared(p);
}
__device__ __forceinline__ void cpasync16(uint32_t dst, const void* src) {
    asm volatile("cp.async.cg.shared.global [%0], [%1], 16;" :: "r"(dst), "l"(src));
}
__device__ __forceinline__ void ldsm4(uint32_t* r, uint32_t addr) {
    asm volatile("ldmatrix.sync.aligned.m8n8.x4.shared.b16 {%0,%1,%2,%3}, [%4];"
                 : "=r"(r[0]), "=r"(r[1]), "=r"(r[2]), "=r"(r[3]) : "r"(addr));
}
__device__ __forceinline__ void ldsm2(uint32_t* r, uint32_t addr) {
    asm volatile("ldmatrix.sync.aligned.m8n8.x2.shared.b16 {%0,%1}, [%2];"
                 : "=r"(r[0]), "=r"(r[1]) : "r"(addr));
}
__device__ __forceinline__ void mma_bf16(float* d, const uint32_t* a, const uint32_t* b) {
    asm volatile(
        "mma.sync.aligned.m16n8k16.row.col.f32.bf16.bf16.f32 "
        "{%0,%1,%2,%3}, {%4,%5,%6,%7}, {%8,%9}, {%0,%1,%2,%3};"
        : "+f"(d[0]), "+f"(d[1]), "+f"(d[2]), "+f"(d[3])
        : "r"(a[0]), "r"(a[1]), "r"(a[2]), "r"(a[3]), "r"(b[0]), "r"(b[1]));
}

__global__ __launch_bounds__(256, 1)
void gemm_dual_kernel(int K, int F,
                      const float* __restrict__ bl, const float* __restrict__ br) {
    extern __shared__ __nv_bfloat16 smem[];
    const int tid  = threadIdx.x;
    const int wid  = tid >> 5, lane = tid & 31;
    const int wm   = wid >> 2;            // 0..1 -> +64 rows
    const int wn   = wid & 3;             // 0..3 -> +32 cols
    const int n0   = blockIdx.x * 128;    // col in [0, 2F)
    const int m0   = blockIdx.y * 128;    // row in [0, NNODE)
    const int side = (n0 >= F) ? 1 : 0;
    float* outp = side ? bufXR : bufXL;
    const float* bp = side ? br : bl;
    const int colBase = n0 - side * F;

    float acc[4][4][4];
    #pragma unroll
    for (int mt = 0; mt < 4; mt++)
        #pragma unroll
        for (int nt = 0; nt < 4; nt++)
            #pragma unroll
            for (int q = 0; q < 4; q++) acc[mt][nt][q] = 0.0f;

    const int aRow = wm * 64 + (lane & 7) + ((lane >> 3) & 1) * 8; // + mt*16
    const int aCol = (lane >> 4) * 8;                              // + ks*16
    const int bRow = wn * 32 + (lane & 7);                         // + nt*8
    const int bCol = ((lane >> 3) & 1) * 8;                        // + ks*16

    // per-thread fixed src row/col for cp.async (4 iters of 256 threads)
    const int nchunk = K >> 6;

    #define ISSUE_CHUNK(stage, c0)                                              \
    {                                                                           \
        __nv_bfloat16* st = smem + (stage) * STAGE_ELEMS;                       \
        _Pragma("unroll")                                                       \
        for (int it = 0; it < 4; it++) {                                        \
            int v = tid + it * 256;                                             \
            int r = v >> 3, c8 = (v & 7) * 8;                                   \
            uint32_t o = s2u(st + r * TSTRIDE + c8);                            \
            size_t ga = (size_t)(m0 + r) * K + (c0) + c8;                       \
            size_t gb = (size_t)(n0 + r) * K + (c0) + c8;                       \
            cpasync16(o,                       bufAhi + ga);                    \
            cpasync16(o + 2 * TILE_ELEMS,      bufAlo + ga);                    \
            cpasync16(o + 4 * TILE_ELEMS,      bufWthi + gb);                   \
            cpasync16(o + 6 * TILE_ELEMS,      bufWtlo + gb);                   \
        }                                                                       \
        asm volatile("cp.async.commit_group;");                                 \
    }

    ISSUE_CHUNK(0, 0)
    for (int c = 0; c < nchunk; c++) {
        if (c + 1 < nchunk) {
            ISSUE_CHUNK((c + 1) & 1, (c + 1) << 6)
            asm volatile("cp.async.wait_group 1;");
        } else {
            asm volatile("cp.async.wait_group 0;");
        }
        __syncthreads();
        __nv_bfloat16* sAhi = smem + (c & 1) * STAGE_ELEMS;
        __nv_bfloat16* sAlo = sAhi + TILE_ELEMS;
        __nv_bfloat16* sBhi = sAhi + 2 * TILE_ELEMS;
        __nv_bfloat16* sBlo = sAhi + 3 * TILE_ELEMS;

        #pragma unroll
        for (int ks = 0; ks < 4; ks++) {
            uint32_t ah[4][4], al[4][4];
            #pragma unroll
            for (int mt = 0; mt < 4; mt++) {
                int off = (aRow + mt * 16) * TSTRIDE + aCol + ks * 16;
                ldsm4(ah[mt], s2u(sAhi + off));
                ldsm4(al[mt], s2u(sAlo + off));
            }
            uint32_t bh[4][2], bo[4][2];
            #pragma unroll
            for (int nt = 0; nt < 4; nt++) {
                int off = (bRow + nt * 8) * TSTRIDE + bCol + ks * 16;
                ldsm2(bh[nt], s2u(sBhi + off));
                ldsm2(bo[nt], s2u(sBlo + off));
            }
            #pragma unroll
            for (int mt = 0; mt < 4; mt++)
                #pragma unroll
                for (int nt = 0; nt < 4; nt++) {
                    mma_bf16(acc[mt][nt], ah[mt], bh[nt]);
                    mma_bf16(acc[mt][nt], al[mt], bh[nt]);
                    mma_bf16(acc[mt][nt], ah[mt], bo[nt]);
                }
        }
        __syncthreads();
    }

    // epilogue: add bias, write XL or XR
    #pragma unroll
    for (int mt = 0; mt < 4; mt++) {
        int r = m0 + wm * 64 + mt * 16 + (lane >> 2);
        #pragma unroll
        for (int nt = 0; nt < 4; nt++) {
            int c = colBase + wn * 32 + nt * 8 + (lane & 3) * 2;
            float b0 = bp[c], b1 = bp[c + 1];
            float* o0 = outp + (size_t)r * F + c;
            o0[0] = acc[mt][nt][0] + b0;
            o0[1] = acc[mt][nt][1] + b1;
            float* o1 = o0 + (size_t)8 * F;
            o1[0] = acc[mt][nt][2] + b0;
            o1[1] = acc[mt][nt][3] + b1;
        }
    }
}

// ---------------- edge logits (float4) ----------------
__global__ void logit_kernel(const float* __restrict__ att, int F) {
    int gid = blockIdx.x * blockDim.x + threadIdx.x;
    int slot = gid >> 5;
    int lane = gid & 31;
    if (slot >= ETOT) return;
    int src = bufCsrSrc[slot];
    int dst = bufCsrDst[slot];
    const float4* pl = (const float4*)(bufXL + (size_t)src * F);
    const float4* pr = (const float4*)(bufXR + (size_t)dst * F);
    const float4* pa = (const float4*)att;
    int nf4 = F >> 2;
    float sum = 0.0f;
    for (int f = lane; f < nf4; f += 32) {
        float4 l = pl[f], r = pr[f], a = pa[f];
        float v0 = l.x + r.x; v0 = (v0 > 0.0f) ? v0 : 0.2f * v0;
        float v1 = l.y + r.y; v1 = (v1 > 0.0f) ? v1 : 0.2f * v1;
        float v2 = l.z + r.z; v2 = (v2 > 0.0f) ? v2 : 0.2f * v2;
        float v3 = l.w + r.w; v3 = (v3 > 0.0f) ? v3 : 0.2f * v3;
        sum = fmaf(v0, a.x, fmaf(v1, a.y, fmaf(v2, a.z, fmaf(v3, a.w, sum))));
    }
    #pragma unroll
    for (int o = 16; o; o >>= 1) sum += __shfl_xor_sync(0xffffffffu, sum, o);
    if (lane == 0) bufE[slot] = sum;
}

// ---------------- per-node segment softmax ----------------
__global__ void softmax_kernel() {
    int gid = blockIdx.x * blockDim.x + threadIdx.x;
    int node = gid >> 5;
    int lane = gid & 31;
    if (node >= NNODE) return;
    int beg = bufRowPtr[node], end = bufRowPtr[node + 1];
    float m = -1e30f;
    for (int s = beg + lane; s < end; s += 32) m = fmaxf(m, bufE[s]);
    #pragma unroll
    for (int o = 16; o; o >>= 1) m = fmaxf(m, __shfl_xor_sync(0xffffffffu, m, o));
    float sum = 0.0f;
    for (int s = beg + lane; s < end; s += 32) sum += __expf(bufE[s] - m);
    #pragma unroll
    for (int o = 16; o; o >>= 1) sum += __shfl_xor_sync(0xffffffffu, sum, o);
    float inv = 1.0f / sum;
    for (int s = beg + lane; s < end; s += 32) bufAlpha[s] = __expf(bufE[s] - m) * inv;
}

// ---------------- aggregation (float4, blockDim = F/4) ----------------
// out[v] = sum alpha*xl[src] + bias; writes split-bf16 next-layer A and/or
// the d_out slice. doRelu applies to both.
__global__ void aggregate_kernel(const float* __restrict__ bias,
                                 int writeNext,                    // 1: write bufAhi/Alo
                                 float* __restrict__ out2,         // may be null
                                 int out2_stride, int F, int doRelu) {
    __shared__ float s_a[256];
    __shared__ int   s_src[256];
    int node = blockIdx.x;
    int tid = threadIdx.x;                 // F/4 threads
    int nt = blockDim.x;
    float4 acc = make_float4(0.0f, 0.0f, 0.0f, 0.0f);

    int beg = bufRowPtr[node], end = bufRowPtr[node + 1];
    for (int c0 = beg; c0 < end; c0 += nt) {
        int cnt = min(nt, end - c0);
        if (tid < cnt) { s_a[tid] = bufAlpha[c0 + tid]; s_src[tid] = bufCsrSrc[c0 + tid]; }
        __syncthreads();
        for (int s = 0; s < cnt; s++) {
            float a = s_a[s];
            const float4* row = (const float4*)(bufXL + (size_t)s_src[s] * F);
            float4 v = row[tid];
            acc.x = fmaf(a, v.x, acc.x);
            acc.y = fmaf(a, v.y, acc.y);
            acc.z = fmaf(a, v.z, acc.z);
            acc.w = fmaf(a, v.w, acc.w);
        }
        __syncthreads();
    }
    float4 b = ((const float4*)bias)[tid];
    float4 v = make_float4(acc.x + b.x, acc.y + b.y, acc.z + b.z, acc.w + b.w);
    if (doRelu) {
        v.x = fmaxf(v.x, 0.0f); v.y = fmaxf(v.y, 0.0f);
        v.z = fmaxf(v.z, 0.0f); v.w = fmaxf(v.w, 0.0f);
    }
    int col = tid * 4;
    if (writeNext) {
        size_t o = (size_t)node * F + col;
        float hx = __bfloat162float(__float2bfloat16(v.x));
        float hy = __bfloat162float(__float2bfloat16(v.y));
        float hz = __bfloat162float(__float2bfloat16(v.z));
        float hw = __bfloat162float(__float2bfloat16(v.w));
        __nv_bfloat162* ph = (__nv_bfloat162*)(bufAhi + o);
        __nv_bfloat162* po = (__nv_bfloat162*)(bufAlo + o);
        ph[0] = __nv_bfloat162(__float2bfloat16(v.x), __float2bfloat16(v.y));
        ph[1] = __nv_bfloat162(__float2bfloat16(v.z), __float2bfloat16(v.w));
        po[0] = __nv_bfloat162(__float2bfloat16(v.x - hx), __float2bfloat16(v.y - hy));
        po[1] = __nv_bfloat162(__float2bfloat16(v.z - hz), __float2bfloat16(v.w - hw));
    }
    if (out2) *(float4*)(out2 + (size_t)node * out2_stride + col) = v;
}

// ---------------- host orchestration ----------------
static void run_gat_layer(int K, int F,
                          const float* Wl, const float* bl,
                          const float* Wr, const float* br,
                          const float* att, const float* bias,
                          int writeNext, float* out2, int doRelu) {
    convertW_kernel<<<(2 * F * K) / 256, 256>>>(Wl, Wr, K, F);
    dim3 ggrid((2 * F) / 128, NNODE / 128);
    gemm_dual_kernel<<<ggrid, 256, SM_TOTAL_G>>>(K, F, bl, br);
    logit_kernel<<<(ETOT * 32 + 255) / 256, 256>>>(att, F);
    softmax_kernel<<<(NNODE * 32) / 256, 256>>>();
    aggregate_kernel<<<NNODE, F / 4>>>(bias, writeNext, out2, OUTC, F, doRelu);
}

extern "C" void kernel_launch(void* const* d_in, const int* in_sizes, int n_in,
                              void* d_out, int out_size) {
    const float* x    = (const float*)d_in[0];
    const float* emb  = (const float*)d_in[1];
    const int*   ei   = (const int*)d_in[2];   // int32 (JAX x64 disabled)
    const float* gw = (const float*)d_in[3];
    const float* gb = (const float*)d_in[4];
    const float* cw = (const float*)d_in[5];
    const float* cb = (const float*)d_in[6];

    const float *Wl[4], *bl[4], *Wr[4], *br[4], *att[4], *bias[4];
    for (int i = 0; i < 4; i++) {
        Wl[i]   = (const float*)d_in[7 + 6 * i + 0];
        bl[i]   = (const float*)d_in[7 + 6 * i + 1];
        Wr[i]   = (const float*)d_in[7 + 6 * i + 2];
        br[i]   = (const float*)d_in[7 + 6 * i + 3];
        att[i]  = (const float*)d_in[7 + 6 * i + 4];
        bias[i] = (const float*)d_in[7 + 6 * i + 5];
    }
    float* out = (float*)d_out;

    cudaFuncSetAttribute(gemm_dual_kernel,
                         cudaFuncAttributeMaxDynamicSharedMemorySize, SM_TOTAL_G);

    // stage 0: fused features (split-bf16 direct) + CSR build
    fuse_kernel<<<NNODE, 128>>>(x, emb, gw, gb, cw, cb);
    zero_deg_kernel<<<NNODE / 256, 256>>>();
    count_kernel<<<(ETOT + 255) / 256, 256>>>(ei);
    scan_kernel<<<1, 1024>>>();
    fill_kernel<<<(ETOT + 255) / 256, 256>>>(ei);

    // 4 GATv2 layers
    run_gat_layer(128,  256, Wl[0], bl[0], Wr[0], br[0], att[0], bias[0],
                  1, out + 0, 1);
    run_gat_layer(256,  512, Wl[1], bl[1], Wr[1], br[1], att[1], bias[1],
                  1, out + 256, 1);
    run_gat_layer(512, 1024, Wl[2], bl[2], Wr[2], br[2], att[2], bias[2],
                  1, nullptr, 1);
    run_gat_layer(1024, 1024, Wl[3], bl[3], Wr[3], br[3], att[3], bias[3],
                  0, out + 768, 0);
}

// round 16
// speedup vs baseline: 2.2273x; 1.0136x over previous
#include <cuda_runtime.h>
#include <cuda_bf16.h>
#include <math.h>
#include <stdint.h>

// ---------------- problem constants ----------------
#define NPTS  2048
#define NNODE 8192                // 4*2048
#define ERAND 131072              // NNODE*16
#define ETOT  (ERAND + NNODE)     // + self loops
#define OUTC  1792                // 256+512+1024
#define KMAX  1024
#define MAXDEG 1024

// ---------------- scratch (static device memory) ----------------
__device__ float bufXL[NNODE * 1024];
__device__ float bufXR[NNODE * 1024];
__device__ __nv_bfloat16 bufAhi[NNODE * KMAX];
__device__ __nv_bfloat16 bufAlo[NNODE * KMAX];
__device__ __nv_bfloat16 bufWthi[2048 * KMAX];   // [2F, K] K-major, Wl^T || Wr^T
__device__ __nv_bfloat16 bufWtlo[2048 * KMAX];
__device__ int   bufDeg[NNODE];
__device__ int   bufRowPtr[NNODE + 1];
__device__ int   bufCursor[NNODE];
__device__ int   bufCsrSrc[ETOT];

// ---------------- fuse: conv1d(3->64) || conv1d(32->64), relu, split-bf16 --
__global__ void fuse_kernel(const float* __restrict__ x,
                            const float* __restrict__ emb,
                            const float* __restrict__ gw, const float* __restrict__ gb,
                            const float* __restrict__ cw, const float* __restrict__ cb) {
    int node = blockIdx.x;
    int b = node / NPTS, n = node % NPTS;
    __shared__ float sx[3];
    __shared__ float se[32];
    int tid = threadIdx.x;              // 128
    if (tid < 3)            sx[tid]    = x[(size_t)b * 3 * NPTS + tid * NPTS + n];
    else if (tid < 35)      se[tid-3]  = emb[(size_t)b * 32 * NPTS + (tid - 3) * NPTS + n];
    __syncthreads();
    float v;
    if (tid < 64) {
        v = gb[tid];
        #pragma unroll
        for (int k = 0; k < 3; k++) v += sx[k] * gw[k * 64 + tid];
    } else {
        int c = tid - 64;
        v = cb[c];
        #pragma unroll
        for (int k = 0; k < 32; k++) v += se[k] * cw[k * 64 + c];
    }
    v = fmaxf(v, 0.0f);
    __nv_bfloat16 hi = __float2bfloat16(v);
    __nv_bfloat16 lo = __float2bfloat16(v - __bfloat162float(hi));
    bufAhi[(size_t)node * 128 + tid] = hi;
    bufAlo[(size_t)node * 128 + tid] = lo;
}

// ---------------- CSR build (edge_index is int32) ----------------
__global__ void zero_deg_kernel() {
    int i = blockIdx.x * blockDim.x + threadIdx.x;
    if (i < NNODE) bufDeg[i] = 0;
}
__global__ void count_kernel(const int* __restrict__ ei) {
    int e = blockIdx.x * blockDim.x + threadIdx.x;
    if (e >= ETOT) return;
    int dst = (e < ERAND) ? ei[ERAND + e] : (e - ERAND);
    atomicAdd(&bufDeg[dst], 1);
}
__global__ void scan_kernel() {
    __shared__ int sh[1024];
    int tid = threadIdx.x;
    int base = tid * 8;
    int local[8];
    int s = 0;
    #pragma unroll
    for (int i = 0; i < 8; i++) { local[i] = s; s += bufDeg[base + i]; }
    sh[tid] = s;
    __syncthreads();
    for (int off = 1; off < 1024; off <<= 1) {
        int v = (tid >= off) ? sh[tid - off] : 0;
        __syncthreads();
        sh[tid] += v;
        __syncthreads();
    }
    int prev = tid ? sh[tid - 1] : 0;
    #pragma unroll
    for (int i = 0; i < 8; i++) {
        bufRowPtr[base + i] = prev + local[i];
        bufCursor[base + i] = prev + local[i];
    }
    if (tid == 1023) bufRowPtr[NNODE] = sh[1023];
}
__global__ void fill_kernel(const int* __restrict__ ei) {
    int e = blockIdx.x * blockDim.x + threadIdx.x;
    if (e >= ETOT) return;
    int src, dst;
    if (e < ERAND) { src = ei[e]; dst = ei[ERAND + e]; }
    else           { src = e - ERAND;  dst = src; }
    int pos = atomicAdd(&bufCursor[dst], 1);
    bufCsrSrc[pos] = src;
}

// ---------------- weight split conversion ----------------
__global__ void convertW_kernel(const float* __restrict__ Wl, const float* __restrict__ Wr,
                                int K, int F) {
    int i = blockIdx.x * blockDim.x + threadIdx.x;
    if (i >= 2 * F * K) return;
    int n = i / K, k = i % K;
    float v = (n < F) ? Wl[(size_t)k * F + n] : Wr[(size_t)k * F + (n - F)];
    __nv_bfloat16 hi = __float2bfloat16(v);
    __nv_bfloat16 lo = __float2bfloat16(v - __bfloat162float(hi));
    bufWthi[i] = hi;
    bufWtlo[i] = lo;
}

// ---------------- mma.sync split-bf16 GEMM, cp.async 2-stage pipeline -----
#define TSTRIDE 72
#define TILE_ELEMS (128 * TSTRIDE)
#define STAGE_ELEMS (4 * TILE_ELEMS)
#define SM_TOTAL_G (2 * STAGE_ELEMS * 2)  // 147456 bytes

__device__ __forceinline__ uint32_t s2u(const void* p) {
    return (uint32_t)__cvta_generic_to_shared(p);
}
__device__ __forceinline__ void cpasync16(uint32_t dst, const void* src) {
    asm volatile("cp.async.cg.shared.global [%0], [%1], 16;" :: "r"(dst), "l"(src));
}
__device__ __forceinline__ void ldsm4(uint32_t* r, uint32_t addr) {
    asm volatile("ldmatrix.sync.aligned.m8n8.x4.shared.b16 {%0,%1,%2,%3}, [%4];"
                 : "=r"(r[0]), "=r"(r[1]), "=r"(r[2]), "=r"(r[3]) : "r"(addr));
}
__device__ __forceinline__ void ldsm2(uint32_t* r, uint32_t addr) {
    asm volatile("ldmatrix.sync.aligned.m8n8.x2.shared.b16 {%0,%1}, [%2];"
                 : "=r"(r[0]), "=r"(r[1]) : "r"(addr));
}
__device__ __forceinline__ void mma_bf16(float* d, const uint32_t* a, const uint32_t* b) {
    asm volatile(
        "mma.sync.aligned.m16n8k16.row.col.f32.bf16.bf16.f32 "
        "{%0,%1,%2,%3}, {%4,%5,%6,%7}, {%8,%9}, {%0,%1,%2,%3};"
        : "+f"(d[0]), "+f"(d[1]), "+f"(d[2]), "+f"(d[3])
        : "r"(a[0]), "r"(a[1]), "r"(a[2]), "r"(a[3]), "r"(b[0]), "r"(b[1]));
}

__global__ __launch_bounds__(256, 1)
void gemm_dual_kernel(int K, int F,
                      const float* __restrict__ bl, const float* __restrict__ br) {
    extern __shared__ __nv_bfloat16 smem[];
    const int tid  = threadIdx.x;
    const int wid  = tid >> 5, lane = tid & 31;
    const int wm   = wid >> 2;
    const int wn   = wid & 3;
    const int n0   = blockIdx.x * 128;
    const int m0   = blockIdx.y * 128;
    const int side = (n0 >= F) ? 1 : 0;
    float* outp = side ? bufXR : bufXL;
    const float* bp = side ? br : bl;
    const int colBase = n0 - side * F;

    float acc[4][4][4];
    #pragma unroll
    for (int mt = 0; mt < 4; mt++)
        #pragma unroll
        for (int nt = 0; nt < 4; nt++)
            #pragma unroll
            for (int q = 0; q < 4; q++) acc[mt][nt][q] = 0.0f;

    const int aRow = wm * 64 + (lane & 7) + ((lane >> 3) & 1) * 8;
    const int aCol = (lane >> 4) * 8;
    const int bRow = wn * 32 + (lane & 7);
    const int bCol = ((lane >> 3) & 1) * 8;

    const int nchunk = K >> 6;

    #define ISSUE_CHUNK(stage, c0)                                              \
    {                                                                           \
        __nv_bfloat16* st = smem + (stage) * STAGE_ELEMS;                       \
        _Pragma("unroll")                                                       \
        for (int it = 0; it < 4; it++) {                                        \
            int v = tid + it * 256;                                             \
            int r = v >> 3, c8 = (v & 7) * 8;                                   \
            uint32_t o = s2u(st + r * TSTRIDE + c8);                            \
            size_t ga = (size_t)(m0 + r) * K + (c0) + c8;                       \
            size_t gb = (size_t)(n0 + r) * K + (c0) + c8;                       \
            cpasync16(o,                       bufAhi + ga);                    \
            cpasync16(o + 2 * TILE_ELEMS,      bufAlo + ga);                    \
            cpasync16(o + 4 * TILE_ELEMS,      bufWthi + gb);                   \
            cpasync16(o + 6 * TILE_ELEMS,      bufWtlo + gb);                   \
        }                                                                       \
        asm volatile("cp.async.commit_group;");                                 \
    }

    ISSUE_CHUNK(0, 0)
    for (int c = 0; c < nchunk; c++) {
        if (c + 1 < nchunk) {
            ISSUE_CHUNK((c + 1) & 1, (c + 1) << 6)
            asm volatile("cp.async.wait_group 1;");
        } else {
            asm volatile("cp.async.wait_group 0;");
        }
        __syncthreads();
        __nv_bfloat16* sAhi = smem + (c & 1) * STAGE_ELEMS;
        __nv_bfloat16* sAlo = sAhi + TILE_ELEMS;
        __nv_bfloat16* sBhi = sAhi + 2 * TILE_ELEMS;
        __nv_bfloat16* sBlo = sAhi + 3 * TILE_ELEMS;

        #pragma unroll
        for (int ks = 0; ks < 4; ks++) {
            uint32_t ah[4][4], al[4][4];
            #pragma unroll
            for (int mt = 0; mt < 4; mt++) {
                int off = (aRow + mt * 16) * TSTRIDE + aCol + ks * 16;
                ldsm4(ah[mt], s2u(sAhi + off));
                ldsm4(al[mt], s2u(sAlo + off));
            }
            uint32_t bh[4][2], bo[4][2];
            #pragma unroll
            for (int nt = 0; nt < 4; nt++) {
                int off = (bRow + nt * 8) * TSTRIDE + bCol + ks * 16;
                ldsm2(bh[nt], s2u(sBhi + off));
                ldsm2(bo[nt], s2u(sBlo + off));
            }
            #pragma unroll
            for (int mt = 0; mt < 4; mt++)
                #pragma unroll
                for (int nt = 0; nt < 4; nt++) {
                    mma_bf16(acc[mt][nt], ah[mt], bh[nt]);
                    mma_bf16(acc[mt][nt], al[mt], bh[nt]);
                    mma_bf16(acc[mt][nt], ah[mt], bo[nt]);
                }
        }
        __syncthreads();
    }

    #pragma unroll
    for (int mt = 0; mt < 4; mt++) {
        int r = m0 + wm * 64 + mt * 16 + (lane >> 2);
        #pragma unroll
        for (int nt = 0; nt < 4; nt++) {
            int c = colBase + wn * 32 + nt * 8 + (lane & 3) * 2;
            float b0 = bp[c], b1 = bp[c + 1];
            float* o0 = outp + (size_t)r * F + c;
            o0[0] = acc[mt][nt][0] + b0;
            o0[1] = acc[mt][nt][1] + b1;
            float* o1 = o0 + (size_t)8 * F;
            o1[0] = acc[mt][nt][2] + b0;
            o1[1] = acc[mt][nt][3] + b1;
        }
    }
}

// ---------------- fused edge stage: logits + softmax + aggregate ----------
// One block per destination node. xr[node] + att cached in smem; edge logits
// warp-parallel; softmax in-block; aggregation thread-per-column.
__global__ __launch_bounds__(256)
void edge_fused_kernel(const float* __restrict__ att,
                       const float* __restrict__ bias,
                       int writeNext, float* __restrict__ out2,
                       int F, int doRelu) {
    __shared__ float s_xr[1024];
    __shared__ float s_att[1024];
    __shared__ float s_e[MAXDEG];
    __shared__ int   s_src[MAXDEG];
    __shared__ float s_red[2];

    const int node = blockIdx.x;
    const int tid = threadIdx.x;
    const int wid = tid >> 5, lane = tid & 31;
    const int beg = bufRowPtr[node];
    int deg = bufRowPtr[node + 1] - beg;
    if (deg > MAXDEG) deg = MAXDEG;

    for (int f = tid; f < F; f += 256) {
        s_xr[f]  = bufXR[(size_t)node * F + f];
        s_att[f] = att[f];
    }
    for (int i = tid; i < deg; i += 256) s_src[i] = bufCsrSrc[beg + i];
    __syncthreads();

    // phase B: warp-per-edge logits
    const int nf4 = F >> 2;
    for (int i = wid; i < deg; i += 8) {
        const float4* pl = (const float4*)(bufXL + (size_t)s_src[i] * F);
        float sum = 0.0f;
        for (int f = lane; f < nf4; f += 32) {
            float4 l = pl[f];
            float4 r = *(const float4*)&s_xr[f * 4];
            float4 a = *(const float4*)&s_att[f * 4];
            float v0 = l.x + r.x; v0 = (v0 > 0.0f) ? v0 : 0.2f * v0;
            float v1 = l.y + r.y; v1 = (v1 > 0.0f) ? v1 : 0.2f * v1;
            float v2 = l.z + r.z; v2 = (v2 > 0.0f) ? v2 : 0.2f * v2;
            float v3 = l.w + r.w; v3 = (v3 > 0.0f) ? v3 : 0.2f * v3;
            sum = fmaf(v0, a.x, fmaf(v1, a.y, fmaf(v2, a.z, fmaf(v3, a.w, sum))));
        }
        #pragma unroll
        for (int o = 16; o; o >>= 1) sum += __shfl_xor_sync(0xffffffffu, sum, o);
        if (lane == 0) s_e[i] = sum;
    }
    __syncthreads();

    // phase C: softmax over deg entries (warp 0)
    if (wid == 0) {
        float m = -1e30f;
        for (int i = lane; i < deg; i += 32) m = fmaxf(m, s_e[i]);
        #pragma unroll
        for (int o = 16; o; o >>= 1) m = fmaxf(m, __shfl_xor_sync(0xffffffffu, m, o));
        float s = 0.0f;
        for (int i = lane; i < deg; i += 32) s += __expf(s_e[i] - m);
        #pragma unroll
        for (int o = 16; o; o >>= 1) s += __shfl_xor_sync(0xffffffffu, s, o);
        if (lane == 0) { s_red[0] = m; s_red[1] = 1.0f / s; }
    }
    __syncthreads();
    {
        float m = s_red[0], inv = s_red[1];
        for (int i = tid; i < deg; i += 256) s_e[i] = __expf(s_e[i] - m) * inv;
    }
    __syncthreads();

    // phase D: accumulate; thread t owns cols t, t+256, ...
    float acc[4] = {0.0f, 0.0f, 0.0f, 0.0f};
    const int nc = F >> 8;                 // 1, 2, or 4
    for (int i = 0; i < deg; i++) {
        float a = s_e[i];
        const float* row = bufXL + (size_t)s_src[i] * F;
        #pragma unroll
        for (int c = 0; c < 4; c++)
            if (c < nc) acc[c] = fmaf(a, row[tid + c * 256], acc[c]);
    }
    #pragma unroll
    for (int c = 0; c < 4; c++) {
        if (c >= nc) break;
        int col = tid + c * 256;
        float v = acc[c] + bias[col];
        if (doRelu) v = fmaxf(v, 0.0f);
        if (writeNext) {
            __nv_bfloat16 hi = __float2bfloat16(v);
            bufAhi[(size_t)node * F + col] = hi;
            bufAlo[(size_t)node * F + col] =
                __float2bfloat16(v - __bfloat162float(hi));
        }
        if (out2) out2[(size_t)node * OUTC + col] = v;
    }
}

// ---------------- host orchestration ----------------
static void run_gat_layer(int K, int F,
                          const float* Wl, const float* bl,
                          const float* Wr, const float* br,
                          const float* att, const float* bias,
                          int writeNext, float* out2, int doRelu) {
    convertW_kernel<<<(2 * F * K) / 256, 256>>>(Wl, Wr, K, F);
    dim3 ggrid((2 * F) / 128, NNODE / 128);
    gemm_dual_kernel<<<ggrid, 256, SM_TOTAL_G>>>(K, F, bl, br);
    edge_fused_kernel<<<NNODE, 256>>>(att, bias, writeNext, out2, F, doRelu);
}

extern "C" void kernel_launch(void* const* d_in, const int* in_sizes, int n_in,
                              void* d_out, int out_size) {
    const float* x    = (const float*)d_in[0];
    const float* emb  = (const float*)d_in[1];
    const int*   ei   = (const int*)d_in[2];   // int32 (JAX x64 disabled)
    const float* gw = (const float*)d_in[3];
    const float* gb = (const float*)d_in[4];
    const float* cw = (const float*)d_in[5];
    const float* cb = (const float*)d_in[6];

    const float *Wl[4], *bl[4], *Wr[4], *br[4], *att[4], *bias[4];
    for (int i = 0; i < 4; i++) {
        Wl[i]   = (const float*)d_in[7 + 6 * i + 0];
        bl[i]   = (const float*)d_in[7 + 6 * i + 1];
        Wr[i]   = (const float*)d_in[7 + 6 * i + 2];
        br[i]   = (const float*)d_in[7 + 6 * i + 3];
        att[i]  = (const float*)d_in[7 + 6 * i + 4];
        bias[i] = (const float*)d_in[7 + 6 * i + 5];
    }
    float* out = (float*)d_out;

    cudaFuncSetAttribute(gemm_dual_kernel,
                         cudaFuncAttributeMaxDynamicSharedMemorySize, SM_TOTAL_G);

    // stage 0: fused features (split-bf16 direct) + CSR build
    fuse_kernel<<<NNODE, 128>>>(x, emb, gw, gb, cw, cb);
    zero_deg_kernel<<<NNODE / 256, 256>>>();
    count_kernel<<<(ETOT + 255) / 256, 256>>>(ei);
    scan_kernel<<<1, 1024>>>();
    fill_kernel<<<(ETOT + 255) / 256, 256>>>(ei);

    // 4 GATv2 layers
    run_gat_layer(128,  256, Wl[0], bl[0], Wr[0], br[0], att[0], bias[0],
                  1, out + 0, 1);
    run_gat_layer(256,  512, Wl[1], bl[1], Wr[1], br[1], att[1], bias[1],
                  1, out + 256, 1);
    run_gat_layer(512, 1024, Wl[2], bl[2], Wr[2], br[2], att[2], bias[2],
                  1, nullptr, 1);
    run_gat_layer(1024, 1024, Wl[3], bl[3], Wr[3], br[3], att[3], bias[3],
                  0, out + 768, 0);
}